// round 11
// baseline (speedup 1.0000x reference)
#include <cuda_runtime.h>
#include <cuda_bf16.h>
#include <cstdint>

// Problem constants
#define B_ 4
#define S_ 1024
#define D_ 1024
#define H_ 16
#define DK_ 64
#define M_TOT (B_ * S_)   // 4096

// Q/K/V in bf16 hi/lo, head-major: [(b*H+h)][s][64], 64-elem rows (128B).
__device__ uint16_t g_Qh[B_ * H_ * S_ * DK_];
__device__ uint16_t g_Ql[B_ * H_ * S_ * DK_];
__device__ uint16_t g_Kh[B_ * H_ * S_ * DK_];
__device__ uint16_t g_Kl[B_ * H_ * S_ * DK_];
__device__ uint16_t g_Vh[B_ * H_ * S_ * DK_];
__device__ uint16_t g_Vl[B_ * H_ * S_ * DK_];
// tf32-pre-converted projection inputs (u32 bit patterns)
__device__ uint32_t g_Xt[3 * M_TOT * D_];
__device__ uint32_t g_Wt[3 * D_ * D_];

// ---------------------------------------------------------------------------
// PTX helpers (baseline sm_80+ features only — target is sm_100 BASE).
// ---------------------------------------------------------------------------
__device__ __forceinline__ uint32_t cvt_tf32(float f) {
    uint32_t r;
    asm("cvt.rna.tf32.f32 %0, %1;" : "=r"(r) : "f"(f));
    return r;
}
__device__ __forceinline__ void cp_async16(void* smem_dst, const void* gmem_src) {
    uint32_t d = (uint32_t)__cvta_generic_to_shared(smem_dst);
    asm volatile("cp.async.ca.shared.global [%0], [%1], 16;"
                 :: "r"(d), "l"(gmem_src) : "memory");
}
#define CP_ASYNC_COMMIT() asm volatile("cp.async.commit_group;" ::: "memory")
#define CP_ASYNC_WAIT1()  asm volatile("cp.async.wait_group 1;" ::: "memory")
#define CP_ASYNC_WAIT2()  asm volatile("cp.async.wait_group 2;" ::: "memory")

__device__ __forceinline__ void mma_tf32(float c[4], const uint32_t a[4],
                                         const uint32_t b[2]) {
    asm volatile(
        "mma.sync.aligned.m16n8k8.row.col.f32.tf32.tf32.f32 "
        "{%0,%1,%2,%3}, {%4,%5,%6,%7}, {%8,%9}, {%0,%1,%2,%3};"
        : "+f"(c[0]), "+f"(c[1]), "+f"(c[2]), "+f"(c[3])
        : "r"(a[0]), "r"(a[1]), "r"(a[2]), "r"(a[3]), "r"(b[0]), "r"(b[1]));
}
__device__ __forceinline__ void mma_bf16(float c[4],
                                         uint32_t a0, uint32_t a1, uint32_t a2, uint32_t a3,
                                         uint32_t b0, uint32_t b1) {
    asm volatile(
        "mma.sync.aligned.m16n8k16.row.col.f32.bf16.bf16.f32 "
        "{%0,%1,%2,%3}, {%4,%5,%6,%7}, {%8,%9}, {%0,%1,%2,%3};"
        : "+f"(c[0]), "+f"(c[1]), "+f"(c[2]), "+f"(c[3])
        : "r"(a0), "r"(a1), "r"(a2), "r"(a3), "r"(b0), "r"(b1));
}
__device__ __forceinline__ void ldmatrix_x4(uint32_t& r0, uint32_t& r1,
                                            uint32_t& r2, uint32_t& r3,
                                            uint32_t smem_addr) {
    asm volatile("ldmatrix.sync.aligned.m8n8.x4.shared.b16 "
                 "{%0,%1,%2,%3}, [%4];"
                 : "=r"(r0), "=r"(r1), "=r"(r2), "=r"(r3) : "r"(smem_addr));
}
__device__ __forceinline__ void ldmatrix_x4_trans(uint32_t& r0, uint32_t& r1,
                                                  uint32_t& r2, uint32_t& r3,
                                                  uint32_t smem_addr) {
    asm volatile("ldmatrix.sync.aligned.m8n8.x4.trans.shared.b16 "
                 "{%0,%1,%2,%3}, [%4];"
                 : "=r"(r0), "=r"(r1), "=r"(r2), "=r"(r3) : "r"(smem_addr));
}
__device__ __forceinline__ uint32_t packbf(float a, float b) {
    __nv_bfloat162 t = __floats2bfloat162_rn(a, b);
    return *reinterpret_cast<uint32_t*>(&t);
}
__device__ __forceinline__ float residf(float a) {
    return a - __bfloat162float(__float2bfloat16(a));
}
// truncation split helpers for P (hot loop): hi = top-16 bits, lo = exact remainder
__device__ __forceinline__ uint32_t packhi16(float a, float b) {
    return __byte_perm(__float_as_uint(a), __float_as_uint(b), 0x7632);
}
__device__ __forceinline__ float trunclo(float a) {
    return a - __uint_as_float(__float_as_uint(a) & 0xFFFF0000u);
}

// head-major index for proj epilogue stores
#define QKV_IDX(row, col) \
    ((((size_t)((row) >> 10) * H_ + ((col) >> 6)) << 16) + \
     (((size_t)((row) & 1023)) << 6) + ((col) & 63))

// ---------------------------------------------------------------------------
// Pre-pass: fp32 -> tf32 bit pattern (u32), float4-vectorized, z picks tensor.
// ---------------------------------------------------------------------------
__global__ void cvt_tf32_kernel(const float* __restrict__ a,
                                const float* __restrict__ b,
                                const float* __restrict__ c,
                                uint32_t* __restrict__ out, int n4) {
    int i = blockIdx.x * blockDim.x + threadIdx.x;
    if (i >= n4) return;
    const float* src = (blockIdx.z == 0) ? a : (blockIdx.z == 1) ? b : c;
    float4 v = ((const float4*)src)[i];
    uint4 r;
    r.x = cvt_tf32(v.x); r.y = cvt_tf32(v.y);
    r.z = cvt_tf32(v.z); r.w = cvt_tf32(v.w);
    ((uint4*)(out + (size_t)blockIdx.z * n4 * 4))[i] = r;
}

// ---------------------------------------------------------------------------
// Projection GEMM via tf32 tensor cores; fragments via ldmatrix-on-u32;
// 3-stage cp.async ring with PBK=32 (prefetch distance 2);
// epilogue emits bf16 hi/lo head-major.
// ---------------------------------------------------------------------------
#define PBM 128
#define PBN 128
#define PBK 32
#define PSTR (PBK + 4)              // 36 u32 row stride — conflict-free ldmatrix
#define PSTAGES 3
#define KSTEPS (D_ / PBK)           // 32
#define P_A_U32  (PBM * PSTR)       // 4608 u32 per A tile
#define P_STG_U32 (2 * P_A_U32)     // 9216 u32 per stage (A then B)
#define PROJ_SMEM (PSTAGES * P_STG_U32 * 4)   // 110592 B

__global__ __launch_bounds__(256, 2)
void qkv_proj_mma(const float* __restrict__ bq,
                  const float* __restrict__ bk,
                  const float* __restrict__ bv) {
    extern __shared__ uint32_t psm[];

    const int z = blockIdx.z;
    const uint32_t* X = g_Xt + (size_t)z * M_TOT * D_;
    const uint32_t* W = g_Wt + (size_t)z * D_ * D_;
    const float* bias = (z == 0) ? bq : (z == 1) ? bk : bv;
    uint16_t* OutH = (z == 0) ? g_Qh : (z == 1) ? g_Kh : g_Vh;
    uint16_t* OutL = (z == 0) ? g_Ql : (z == 1) ? g_Kl : g_Vl;

    const int t   = threadIdx.x;
    const int wid = t >> 5;
    const int lid = t & 31;
    const int lr  = lid >> 2;
    const int lc  = lid & 3;
    const int wm  = wid & 1;
    const int wn  = wid >> 1;
    const int m0  = blockIdx.y * PBM;
    const int n0  = blockIdx.x * PBN;

    // ldmatrix lane addressing for 32-bit fragments
    const int a_r = ((lid >> 3) & 1) * 8 + (lid & 7);
    const int a_c = (lid >> 4) * 4;
    const int b_r = (lid >> 4) * 8 + (lid & 7);
    const int b_c = ((lid >> 3) & 1) * 4;

    float acc[4][4][4];
    #pragma unroll
    for (int i = 0; i < 4; i++)
        #pragma unroll
        for (int j = 0; j < 4; j++)
            #pragma unroll
            for (int r = 0; r < 4; r++) acc[i][j][r] = 0.f;

    // Fill one stage: 128 rows x 8 16B-chunks per matrix = 1024 jobs each;
    // 4 A-jobs + 4 B-jobs per thread.
    auto load_stage = [&](int st, int ks) {
        const int k0 = ks * PBK;
        uint32_t* A = psm + st * P_STG_U32;
        uint32_t* Bm = A + P_A_U32;
        #pragma unroll
        for (int i = 0; i < 4; i++) {
            int job = t + i * 256;          // 0..1023
            int row = job >> 3;             // 0..127
            int ch  = (job & 7) * 4;        // u32 offset 0,4,...,28
            cp_async16(&A[row * PSTR + ch],  &X[(size_t)(m0 + row) * D_ + k0 + ch]);
            cp_async16(&Bm[row * PSTR + ch], &W[(size_t)(n0 + row) * D_ + k0 + ch]);
        }
    };

    load_stage(0, 0);
    CP_ASYNC_COMMIT();
    load_stage(1, 1);
    CP_ASYNC_COMMIT();

    int st = 0;
    for (int ks = 0; ks < KSTEPS; ks++) {
        if (ks + 2 < KSTEPS) {
            int nst = st + 2; if (nst >= PSTAGES) nst -= PSTAGES;
            load_stage(nst, ks + 2);
        }
        CP_ASYNC_COMMIT();                 // empty group near the end keeps math
        CP_ASYNC_WAIT2();                  // stage ks resident
        __syncthreads();

        const uint32_t* A = psm + st * P_STG_U32;
        const uint32_t* Bm = A + P_A_U32;

        #pragma unroll
        for (int kk = 0; kk < PBK; kk += 8) {
            uint32_t a[4][4], b[4][2];
            #pragma unroll
            for (int mf = 0; mf < 4; mf++) {
                uint32_t ad = (uint32_t)__cvta_generic_to_shared(
                    &A[(wm * 64 + mf * 16 + a_r) * PSTR + kk + a_c]);
                ldmatrix_x4(a[mf][0], a[mf][1], a[mf][2], a[mf][3], ad);
            }
            #pragma unroll
            for (int np = 0; np < 2; np++) {
                uint32_t bd = (uint32_t)__cvta_generic_to_shared(
                    &Bm[(wn * 32 + np * 16 + b_r) * PSTR + kk + b_c]);
                ldmatrix_x4(b[2 * np][0], b[2 * np][1],
                            b[2 * np + 1][0], b[2 * np + 1][1], bd);
            }
            #pragma unroll
            for (int mf = 0; mf < 4; mf++)
                #pragma unroll
                for (int nf = 0; nf < 4; nf++)
                    mma_tf32(acc[mf][nf], a[mf], b[nf]);
        }
        __syncthreads();                   // stage st consumed; safe to refill
        if (++st >= PSTAGES) st = 0;
    }

    // Epilogue: bias add, split to bf16 hi/lo, store head-major.
    #pragma unroll
    for (int mf = 0; mf < 4; mf++) {
        int row = m0 + wm * 64 + mf * 16 + lr;
        #pragma unroll
        for (int nf = 0; nf < 4; nf++) {
            int col = n0 + wn * 32 + nf * 8 + lc * 2;
            float2 bv2 = *(const float2*)&bias[col];
            float v00 = acc[mf][nf][0] + bv2.x;
            float v01 = acc[mf][nf][1] + bv2.y;
            float v10 = acc[mf][nf][2] + bv2.x;
            float v11 = acc[mf][nf][3] + bv2.y;
            size_t i0 = QKV_IDX(row, col);
            size_t i1 = QKV_IDX(row + 8, col);
            *(uint32_t*)&OutH[i0] = packbf(v00, v01);
            *(uint32_t*)&OutL[i0] = packbf(residf(v00), residf(v01));
            *(uint32_t*)&OutH[i1] = packbf(v10, v11);
            *(uint32_t*)&OutL[i1] = packbf(residf(v10), residf(v11));
        }
    }
}

// ---------------------------------------------------------------------------
// Flash attention, bf16 MMA + hi/lo compensation, log2-domain softmax.
// (unchanged from R10 — proven 148.6us)
// ---------------------------------------------------------------------------
#define RSTR 72                       // row stride in ushorts (144B)
#define SM_QH 0
#define SM_QL 18432
#define SM_KV 36864                   // 2 stages of {Kh,Kl,Vh,Vl}
#define KV_STAGE 36864
#define OFF_KH 0
#define OFF_KL 9216
#define OFF_VH 18432
#define OFF_VL 27648
#define SM_MK (SM_KV + 2 * KV_STAGE)  // 110592; 2 x 256B mask stages
#define ATTN_SMEM (SM_MK + 512)       // 111104

__global__ __launch_bounds__(256, 2)
void attn_mma(const int* __restrict__ mask, float* __restrict__ out) {
    extern __shared__ char sm[];

    const int qb = (int)(gridDim.x - 1) - (int)blockIdx.x;   // heavy blocks first
    const int h  = blockIdx.y;
    const int b  = blockIdx.z;
    const int q0 = qb * 128;
    const int t  = threadIdx.x;
    const int w  = t >> 5;
    const int lid = t & 31;
    const int lr = lid >> 2;
    const int lc = lid & 3;
    const float SCL = 0.125f * 1.4426950408889634f;

    const size_t hb = ((size_t)(b * H_ + h)) << 16;
    const uint16_t* Qhg = g_Qh + hb;
    const uint16_t* Qlg = g_Ql + hb;
    const uint16_t* Khg = g_Kh + hb;
    const uint16_t* Klg = g_Kl + hb;
    const uint16_t* Vhg = g_Vh + hb;
    const uint16_t* Vlg = g_Vl + hb;
    const int* mrow = mask + b * S_;

    const uint32_t smb = (uint32_t)__cvta_generic_to_shared(sm);
    const int lrow8 = (lid & 7) + (lid & 8);
    const int lcol8 = (lid >> 4) << 3;

    {
        int row = t >> 1, half = (t & 1) * 32;
        size_t g = ((size_t)(q0 + row) << 6) + half;
        uint32_t so = (uint32_t)(row * RSTR + half) * 2;
        #pragma unroll
        for (int i = 0; i < 4; i++) {
            cp_async16(sm + SM_QH + so + i * 16, Qhg + g + i * 8);
            cp_async16(sm + SM_QL + so + i * 16, Qlg + g + i * 8);
        }
    }
    CP_ASYNC_COMMIT();

    auto load_kv = [&](int st, int kt) {
        int r = t >> 2, seg = t & 3;
        size_t g = ((size_t)(kt * 64 + r) << 6) + seg * 16;
        char* stb = sm + SM_KV + st * KV_STAGE;
        uint32_t so = (uint32_t)(r * RSTR + seg * 16) * 2;
        cp_async16(stb + OFF_KH + so,      Khg + g);
        cp_async16(stb + OFF_KH + so + 16, Khg + g + 8);
        cp_async16(stb + OFF_KL + so,      Klg + g);
        cp_async16(stb + OFF_KL + so + 16, Klg + g + 8);
        cp_async16(stb + OFF_VH + so,      Vhg + g);
        cp_async16(stb + OFF_VH + so + 16, Vhg + g + 8);
        cp_async16(stb + OFF_VL + so,      Vlg + g);
        cp_async16(stb + OFF_VL + so + 16, Vlg + g + 8);
        if (t < 16)
            cp_async16(sm + SM_MK + st * 256 + t * 16, mrow + kt * 64 + t * 4);
    };

    load_kv(0, 0);
    CP_ASYNC_COMMIT();

    float o[8][4];
    #pragma unroll
    for (int i = 0; i < 8; i++)
        #pragma unroll
        for (int j = 0; j < 4; j++) o[i][j] = 0.f;
    float m0 = -1.0e30f, m1 = -1.0e30f, l0 = 0.f, l1 = 0.f;

    const int gr0 = q0 + w * 16 + lr;
    const int ntiles = 2 * qb + 2;

    for (int kt = 0; kt < ntiles; kt++) {
        const int st = kt & 1;
        if (kt + 1 < ntiles) load_kv(st ^ 1, kt + 1);
        CP_ASYNC_COMMIT();
        CP_ASYNC_WAIT1();
        __syncthreads();

        const bool active = (kt * 64 <= q0 + w * 16 + 15);
        if (active) {
            const uint32_t kh32 = smb + SM_KV + st * KV_STAGE + OFF_KH;
            const uint32_t kl32 = smb + SM_KV + st * KV_STAGE + OFF_KL;
            const uint32_t vh32 = smb + SM_KV + st * KV_STAGE + OFF_VH;
            const uint32_t vl32 = smb + SM_KV + st * KV_STAGE + OFF_VL;
            const int* mk = (const int*)(sm + SM_MK + st * 256);

            int rem = q0 + w * 16 + 15 - kt * 64;
            if (rem > 63) rem = 63;
            const int nlim = (rem >> 4) + 1;

            float s[8][4];
            #pragma unroll
            for (int i = 0; i < 8; i++)
                #pragma unroll
                for (int j = 0; j < 4; j++) s[i][j] = 0.f;

            #pragma unroll
            for (int ks = 0; ks < 4; ks++) {
                const int ko = ks * 16;
                const uint32_t afo =
                    (uint32_t)((w * 16 + lrow8) * RSTR + ko + lcol8) * 2;
                uint32_t ah0, ah1, ah2, ah3, al0, al1, al2, al3;
                ldmatrix_x4(ah0, ah1, ah2, ah3, smb + SM_QH + afo);
                ldmatrix_x4(al0, al1, al2, al3, smb + SM_QL + afo);
                #pragma unroll
                for (int nfp = 0; nfp < 4; nfp++) {
                    if (nfp < nlim) {
                        const uint32_t bfo =
                            (uint32_t)((nfp * 16 + lrow8) * RSTR + ko + lcol8) * 2;
                        uint32_t bh0, bh1, bh2, bh3, bl0, bl1, bl2, bl3;
                        ldmatrix_x4(bh0, bh1, bh2, bh3, kh32 + bfo);
                        ldmatrix_x4(bl0, bl1, bl2, bl3, kl32 + bfo);
                        mma_bf16(s[2*nfp],   ah0, ah1, ah2, ah3, bh0, bh2);
                        mma_bf16(s[2*nfp],   ah0, ah1, ah2, ah3, bl0, bl2);
                        mma_bf16(s[2*nfp],   al0, al1, al2, al3, bh0, bh2);
                        mma_bf16(s[2*nfp+1], ah0, ah1, ah2, ah3, bh1, bh3);
                        mma_bf16(s[2*nfp+1], ah0, ah1, ah2, ah3, bl1, bl3);
                        mma_bf16(s[2*nfp+1], al0, al1, al2, al3, bh1, bh3);
                    }
                }
            }

            const bool diag = (kt >= 2 * qb);
            #pragma unroll
            for (int nf = 0; nf < 8; nf++) {
                int ci  = nf * 8 + 2 * lc;
                int c0  = kt * 64 + ci, c1 = c0 + 1;
                int mv0 = mk[ci], mv1 = mk[ci + 1];
                float v;
                v = s[nf][0] * SCL;
                if ((diag && c0 > gr0) || mv0 == 0) v = -1.0e30f;
                s[nf][0] = v;
                v = s[nf][1] * SCL;
                if ((diag && c1 > gr0) || mv1 == 0) v = -1.0e30f;
                s[nf][1] = v;
                v = s[nf][2] * SCL;
                if ((diag && c0 > gr0 + 8) || mv0 == 0) v = -1.0e30f;
                s[nf][2] = v;
                v = s[nf][3] * SCL;
                if ((diag && c1 > gr0 + 8) || mv1 == 0) v = -1.0e30f;
                s[nf][3] = v;
            }

            float mx0 = -1.0e30f, mx1 = -1.0e30f;
            #pragma unroll
            for (int nf = 0; nf < 8; nf++) {
                mx0 = fmaxf(mx0, fmaxf(s[nf][0], s[nf][1]));
                mx1 = fmaxf(mx1, fmaxf(s[nf][2], s[nf][3]));
            }
            mx0 = fmaxf(mx0, __shfl_xor_sync(0xffffffffu, mx0, 1));
            mx0 = fmaxf(mx0, __shfl_xor_sync(0xffffffffu, mx0, 2));
            mx1 = fmaxf(mx1, __shfl_xor_sync(0xffffffffu, mx1, 1));
            mx1 = fmaxf(mx1, __shfl_xor_sync(0xffffffffu, mx1, 2));
            float mn0 = fmaxf(m0, mx0), mn1 = fmaxf(m1, mx1);
            float alpha0 = exp2f(m0 - mn0), alpha1 = exp2f(m1 - mn1);
            m0 = mn0; m1 = mn1;

            float sum0 = 0.f, sum1 = 0.f;
            #pragma unroll
            for (int nf = 0; nf < 8; nf++) {
                float p;
                p = exp2f(s[nf][0] - mn0); s[nf][0] = p; sum0 += p;
                p = exp2f(s[nf][1] - mn0); s[nf][1] = p; sum0 += p;
                p = exp2f(s[nf][2] - mn1); s[nf][2] = p; sum1 += p;
                p = exp2f(s[nf][3] - mn1); s[nf][3] = p; sum1 += p;
            }
            sum0 += __shfl_xor_sync(0xffffffffu, sum0, 1);
            sum0 += __shfl_xor_sync(0xffffffffu, sum0, 2);
            sum1 += __shfl_xor_sync(0xffffffffu, sum1, 1);
            sum1 += __shfl_xor_sync(0xffffffffu, sum1, 2);
            l0 = l0 * alpha0 + sum0;
            l1 = l1 * alpha1 + sum1;

            #pragma unroll
            for (int nf = 0; nf < 8; nf++) {
                o[nf][0] *= alpha0; o[nf][1] *= alpha0;
                o[nf][2] *= alpha1; o[nf][3] *= alpha1;
            }

            const int g  = lid >> 3;
            const int lrow = lid & 7;
            #pragma unroll
            for (int ks = 0; ks < 4; ks++) {
                if (ks < nlim) {
                    uint32_t ph0 = packhi16(s[2*ks][0],   s[2*ks][1]);
                    uint32_t ph1 = packhi16(s[2*ks][2],   s[2*ks][3]);
                    uint32_t ph2 = packhi16(s[2*ks+1][0], s[2*ks+1][1]);
                    uint32_t ph3 = packhi16(s[2*ks+1][2], s[2*ks+1][3]);
                    uint32_t pl0 = packbf(trunclo(s[2*ks][0]),   trunclo(s[2*ks][1]));
                    uint32_t pl1 = packbf(trunclo(s[2*ks][2]),   trunclo(s[2*ks][3]));
                    uint32_t pl2 = packbf(trunclo(s[2*ks+1][0]), trunclo(s[2*ks+1][1]));
                    uint32_t pl3 = packbf(trunclo(s[2*ks+1][2]), trunclo(s[2*ks+1][3]));
                    #pragma unroll
                    for (int nfp = 0; nfp < 4; nfp++) {
                        uint32_t offB = (uint32_t)((ks * 16 + (g & 1) * 8 + lrow) * RSTR
                                                   + nfp * 16 + (g >> 1) * 8) * 2;
                        uint32_t bh0, bh1, bh2, bh3, bl0, bl1, bl2, bl3;
                        ldmatrix_x4_trans(bh0, bh1, bh2, bh3, vh32 + offB);
                        ldmatrix_x4_trans(bl0, bl1, bl2, bl3, vl32 + offB);
                        mma_bf16(o[2*nfp],   ph0, ph1, ph2, ph3, bh0, bh1);
                        mma_bf16(o[2*nfp],   ph0, ph1, ph2, ph3, bl0, bl1);
                        mma_bf16(o[2*nfp],   pl0, pl1, pl2, pl3, bh0, bh1);
                        mma_bf16(o[2*nfp+1], ph0, ph1, ph2, ph3, bh2, bh3);
                        mma_bf16(o[2*nfp+1], ph0, ph1, ph2, ph3, bl2, bl3);
                        mma_bf16(o[2*nfp+1], pl0, pl1, pl2, pl3, bh2, bh3);
                    }
                }
            }
        }
        __syncthreads();
    }

    float inv0 = 1.0f / l0, inv1 = 1.0f / l1;
    #pragma unroll
    for (int nf = 0; nf < 8; nf++) {
        int col = h * DK_ + nf * 8 + 2 * lc;
        float2 r0, r1;
        r0.x = o[nf][0] * inv0; r0.y = o[nf][1] * inv0;
        r1.x = o[nf][2] * inv1; r1.y = o[nf][3] * inv1;
        *(float2*)&out[(size_t)(b * S_ + gr0) * D_ + col] = r0;
        *(float2*)&out[(size_t)(b * S_ + gr0 + 8) * D_ + col] = r1;
    }
}

// ---------------------------------------------------------------------------
// Launch
// inputs: query, key, value, att_mask, Wq, bq, Wk, bk, Wv, bv
// ---------------------------------------------------------------------------
extern "C" void kernel_launch(void* const* d_in, const int* in_sizes, int n_in,
                              void* d_out, int out_size) {
    (void)in_sizes; (void)n_in; (void)out_size;
    const float* query = (const float*)d_in[0];
    const float* key   = (const float*)d_in[1];
    const float* value = (const float*)d_in[2];
    const int*   amask = (const int*)  d_in[3];
    const float* Wq = (const float*)d_in[4];
    const float* bq = (const float*)d_in[5];
    const float* Wk = (const float*)d_in[6];
    const float* bk = (const float*)d_in[7];
    const float* Wv = (const float*)d_in[8];
    const float* bv = (const float*)d_in[9];
    float* out = (float*)d_out;

    static uint32_t *xt = nullptr, *wt = nullptr;
    if (!xt) {
        cudaGetSymbolAddress((void**)&xt, g_Xt);
        cudaGetSymbolAddress((void**)&wt, g_Wt);
        cudaFuncSetAttribute(qkv_proj_mma,
                             cudaFuncAttributeMaxDynamicSharedMemorySize, PROJ_SMEM);
        cudaFuncSetAttribute(attn_mma,
                             cudaFuncAttributeMaxDynamicSharedMemorySize, ATTN_SMEM);
    }

    const int NX4 = M_TOT * D_ / 4;   // 1048576
    const int NW4 = D_ * D_ / 4;      // 262144
    dim3 gx((NX4 + 255) / 256, 1, 3);
    cvt_tf32_kernel<<<gx, 256>>>(query, key, value, xt, NX4);
    dim3 gw((NW4 + 255) / 256, 1, 3);
    cvt_tf32_kernel<<<gw, 256>>>(Wq, Wk, Wv, wt, NW4);

    dim3 gproj(D_ / PBN, M_TOT / PBM, 3);   // (8, 32, 3)
    qkv_proj_mma<<<gproj, 256, PROJ_SMEM>>>(bq, bk, bv);

    dim3 gattn(S_ / 128, H_, B_);            // (8, 16, 4)
    attn_mma<<<gattn, 256, ATTN_SMEM>>>(amask, out);
}

// round 12
// speedup vs baseline: 1.3390x; 1.3390x over previous
#include <cuda_runtime.h>
#include <cuda_bf16.h>
#include <cuda_fp16.h>
#include <cstdint>

// Problem constants
#define B_ 4
#define S_ 1024
#define D_ 1024
#define H_ 16
#define DK_ 64
#define M_TOT (B_ * S_)   // 4096

// Q/K/V in bf16 hi/lo, head-major: [(b*H+h)][s][64], 64-elem rows (128B).
__device__ uint16_t g_Qh[B_ * H_ * S_ * DK_];
__device__ uint16_t g_Ql[B_ * H_ * S_ * DK_];
__device__ uint16_t g_Kh[B_ * H_ * S_ * DK_];
__device__ uint16_t g_Kl[B_ * H_ * S_ * DK_];
__device__ uint16_t g_Vh[B_ * H_ * S_ * DK_];
__device__ uint16_t g_Vl[B_ * H_ * S_ * DK_];
// fp16-pre-converted projection inputs
__device__ uint16_t g_X16[3 * M_TOT * D_];
__device__ uint16_t g_W16[3 * D_ * D_];

// ---------------------------------------------------------------------------
// PTX helpers (baseline sm_80+ features only — target is sm_100 BASE).
// ---------------------------------------------------------------------------
__device__ __forceinline__ void cp_async16(void* smem_dst, const void* gmem_src) {
    uint32_t d = (uint32_t)__cvta_generic_to_shared(smem_dst);
    asm volatile("cp.async.ca.shared.global [%0], [%1], 16;"
                 :: "r"(d), "l"(gmem_src) : "memory");
}
#define CP_ASYNC_COMMIT() asm volatile("cp.async.commit_group;" ::: "memory")
#define CP_ASYNC_WAIT1()  asm volatile("cp.async.wait_group 1;" ::: "memory")

// fp16 m16n8k16, fp32 accumulate
__device__ __forceinline__ void mma_f16(float c[4],
                                        uint32_t a0, uint32_t a1, uint32_t a2, uint32_t a3,
                                        uint32_t b0, uint32_t b1) {
    asm volatile(
        "mma.sync.aligned.m16n8k16.row.col.f32.f16.f16.f32 "
        "{%0,%1,%2,%3}, {%4,%5,%6,%7}, {%8,%9}, {%0,%1,%2,%3};"
        : "+f"(c[0]), "+f"(c[1]), "+f"(c[2]), "+f"(c[3])
        : "r"(a0), "r"(a1), "r"(a2), "r"(a3), "r"(b0), "r"(b1));
}
__device__ __forceinline__ void mma_bf16(float c[4],
                                         uint32_t a0, uint32_t a1, uint32_t a2, uint32_t a3,
                                         uint32_t b0, uint32_t b1) {
    asm volatile(
        "mma.sync.aligned.m16n8k16.row.col.f32.bf16.bf16.f32 "
        "{%0,%1,%2,%3}, {%4,%5,%6,%7}, {%8,%9}, {%0,%1,%2,%3};"
        : "+f"(c[0]), "+f"(c[1]), "+f"(c[2]), "+f"(c[3])
        : "r"(a0), "r"(a1), "r"(a2), "r"(a3), "r"(b0), "r"(b1));
}
__device__ __forceinline__ void ldmatrix_x4(uint32_t& r0, uint32_t& r1,
                                            uint32_t& r2, uint32_t& r3,
                                            uint32_t smem_addr) {
    asm volatile("ldmatrix.sync.aligned.m8n8.x4.shared.b16 "
                 "{%0,%1,%2,%3}, [%4];"
                 : "=r"(r0), "=r"(r1), "=r"(r2), "=r"(r3) : "r"(smem_addr));
}
__device__ __forceinline__ void ldmatrix_x4_trans(uint32_t& r0, uint32_t& r1,
                                                  uint32_t& r2, uint32_t& r3,
                                                  uint32_t smem_addr) {
    asm volatile("ldmatrix.sync.aligned.m8n8.x4.trans.shared.b16 "
                 "{%0,%1,%2,%3}, [%4];"
                 : "=r"(r0), "=r"(r1), "=r"(r2), "=r"(r3) : "r"(smem_addr));
}
__device__ __forceinline__ uint32_t packbf(float a, float b) {
    __nv_bfloat162 t = __floats2bfloat162_rn(a, b);
    return *reinterpret_cast<uint32_t*>(&t);
}
__device__ __forceinline__ uint32_t packhf(float a, float b) {
    __half2 t = __floats2half2_rn(a, b);
    return *reinterpret_cast<uint32_t*>(&t);
}
__device__ __forceinline__ float residf(float a) {
    return a - __bfloat162float(__float2bfloat16(a));
}
// truncation split helpers for P (hot loop)
__device__ __forceinline__ uint32_t packhi16(float a, float b) {
    return __byte_perm(__float_as_uint(a), __float_as_uint(b), 0x7632);
}
__device__ __forceinline__ float trunclo(float a) {
    return a - __uint_as_float(__float_as_uint(a) & 0xFFFF0000u);
}

// head-major index for proj epilogue stores
#define QKV_IDX(row, col) \
    ((((size_t)((row) >> 10) * H_ + ((col) >> 6)) << 16) + \
     (((size_t)((row) & 1023)) << 6) + ((col) & 63))

// ---------------------------------------------------------------------------
// Pre-pass: fp32 -> fp16, float4-vectorized, z picks tensor.
// ---------------------------------------------------------------------------
__global__ void cvt_f16_kernel(const float* __restrict__ a,
                               const float* __restrict__ b,
                               const float* __restrict__ c,
                               uint16_t* __restrict__ out, int n4) {
    int i = blockIdx.x * blockDim.x + threadIdx.x;
    if (i >= n4) return;
    const float* src = (blockIdx.z == 0) ? a : (blockIdx.z == 1) ? b : c;
    float4 v = ((const float4*)src)[i];
    uint2 r;
    r.x = packhf(v.x, v.y);
    r.y = packhf(v.z, v.w);
    ((uint2*)(out + (size_t)blockIdx.z * n4 * 4))[i] = r;
}

// ---------------------------------------------------------------------------
// Projection GEMM via fp16 m16n8k16 (single pass — fp16 mantissa == tf32
// mantissa, but 2x K-depth per mma instruction). 2-stage cp.async, PBK=32.
// Epilogue emits bf16 hi/lo head-major.
// ---------------------------------------------------------------------------
#define PBM 128
#define PBN 128
#define PBK 32
#define PROW 40                     // ushort row stride (80B) — conflict-free
#define KSTEPS (D_ / PBK)           // 32
#define P_A_USH (PBM * PROW)        // 5120 ushorts per A tile

__global__ __launch_bounds__(256, 2)
void qkv_proj_mma(const float* __restrict__ bq,
                  const float* __restrict__ bk,
                  const float* __restrict__ bv) {
    __shared__ uint16_t As[2][P_A_USH];
    __shared__ uint16_t Bs[2][P_A_USH];

    const int z = blockIdx.z;
    const uint16_t* X = g_X16 + (size_t)z * M_TOT * D_;
    const uint16_t* W = g_W16 + (size_t)z * D_ * D_;
    const float* bias = (z == 0) ? bq : (z == 1) ? bk : bv;
    uint16_t* OutH = (z == 0) ? g_Qh : (z == 1) ? g_Kh : g_Vh;
    uint16_t* OutL = (z == 0) ? g_Ql : (z == 1) ? g_Kl : g_Vl;

    const int t   = threadIdx.x;
    const int wid = t >> 5;
    const int lid = t & 31;
    const int lr  = lid >> 2;
    const int lc  = lid & 3;
    const int wm  = wid & 1;
    const int wn  = wid >> 1;
    const int m0  = blockIdx.y * PBM;
    const int n0  = blockIdx.x * PBN;

    // b16 ldmatrix lane addressing (same formula proven in attn kernel)
    const int lrow8 = (lid & 7) + (lid & 8);          // 0..15
    const int lcol8 = (lid >> 4) << 3;                // 0 or 8

    float acc[4][4][4];
    #pragma unroll
    for (int i = 0; i < 4; i++)
        #pragma unroll
        for (int j = 0; j < 4; j++)
            #pragma unroll
            for (int r = 0; r < 4; r++) acc[i][j][r] = 0.f;

    // Fill one stage: 128 rows x 4 16B-chunks per matrix = 512 jobs each;
    // 2 A-jobs + 2 B-jobs per thread.
    auto load_stage = [&](int s, int ks) {
        const int k0 = ks * PBK;
        #pragma unroll
        for (int i = 0; i < 2; i++) {
            int job = t + i * 256;          // 0..511
            int row = job >> 2;             // 0..127
            int ch  = (job & 3) * 8;        // ushort offset 0,8,16,24
            cp_async16(&As[s][row * PROW + ch], &X[(size_t)(m0 + row) * D_ + k0 + ch]);
            cp_async16(&Bs[s][row * PROW + ch], &W[(size_t)(n0 + row) * D_ + k0 + ch]);
        }
    };

    load_stage(0, 0);
    CP_ASYNC_COMMIT();

    for (int ks = 0; ks < KSTEPS; ks++) {
        const int s = ks & 1;
        if (ks + 1 < KSTEPS) load_stage(s ^ 1, ks + 1);
        CP_ASYNC_COMMIT();
        CP_ASYNC_WAIT1();
        __syncthreads();

        #pragma unroll
        for (int kh = 0; kh < 2; kh++) {              // two k16 halves
            const int ko = kh * 16;
            uint32_t a[4][4], b[4][2];
            #pragma unroll
            for (int mf = 0; mf < 4; mf++) {
                uint32_t ad = (uint32_t)__cvta_generic_to_shared(
                    &As[s][(wm * 64 + mf * 16 + lrow8) * PROW + ko + lcol8]);
                ldmatrix_x4(a[mf][0], a[mf][1], a[mf][2], a[mf][3], ad);
            }
            #pragma unroll
            for (int np = 0; np < 2; np++) {          // n16 tile -> two n8 frags
                uint32_t bd = (uint32_t)__cvta_generic_to_shared(
                    &Bs[s][(wn * 32 + np * 16 + lrow8) * PROW + ko + lcol8]);
                uint32_t b0, b1, b2, b3;
                ldmatrix_x4(b0, b1, b2, b3, bd);
                b[2 * np][0] = b0; b[2 * np][1] = b2;       // n rows 0-7
                b[2 * np + 1][0] = b1; b[2 * np + 1][1] = b3; // n rows 8-15
            }
            #pragma unroll
            for (int mf = 0; mf < 4; mf++)
                #pragma unroll
                for (int nf = 0; nf < 4; nf++)
                    mma_f16(acc[mf][nf], a[mf][0], a[mf][1], a[mf][2], a[mf][3],
                            b[nf][0], b[nf][1]);
        }
        __syncthreads();
    }

    // Epilogue: bias add, split to bf16 hi/lo, store head-major.
    #pragma unroll
    for (int mf = 0; mf < 4; mf++) {
        int row = m0 + wm * 64 + mf * 16 + lr;
        #pragma unroll
        for (int nf = 0; nf < 4; nf++) {
            int col = n0 + wn * 32 + nf * 8 + lc * 2;
            float2 bv2 = *(const float2*)&bias[col];
            float v00 = acc[mf][nf][0] + bv2.x;
            float v01 = acc[mf][nf][1] + bv2.y;
            float v10 = acc[mf][nf][2] + bv2.x;
            float v11 = acc[mf][nf][3] + bv2.y;
            size_t i0 = QKV_IDX(row, col);
            size_t i1 = QKV_IDX(row + 8, col);
            *(uint32_t*)&OutH[i0] = packbf(v00, v01);
            *(uint32_t*)&OutL[i0] = packbf(residf(v00), residf(v01));
            *(uint32_t*)&OutH[i1] = packbf(v10, v11);
            *(uint32_t*)&OutL[i1] = packbf(residf(v10), residf(v11));
        }
    }
}

// ---------------------------------------------------------------------------
// Flash attention, bf16 MMA + hi/lo compensation, log2-domain softmax.
// (unchanged from R10 — proven 148.6us)
// ---------------------------------------------------------------------------
#define RSTR 72                       // row stride in ushorts (144B)
#define SM_QH 0
#define SM_QL 18432
#define SM_KV 36864                   // 2 stages of {Kh,Kl,Vh,Vl}
#define KV_STAGE 36864
#define OFF_KH 0
#define OFF_KL 9216
#define OFF_VH 18432
#define OFF_VL 27648
#define SM_MK (SM_KV + 2 * KV_STAGE)  // 110592; 2 x 256B mask stages
#define ATTN_SMEM (SM_MK + 512)       // 111104

__global__ __launch_bounds__(256, 2)
void attn_mma(const int* __restrict__ mask, float* __restrict__ out) {
    extern __shared__ char sm[];

    const int qb = (int)(gridDim.x - 1) - (int)blockIdx.x;   // heavy blocks first
    const int h  = blockIdx.y;
    const int b  = blockIdx.z;
    const int q0 = qb * 128;
    const int t  = threadIdx.x;
    const int w  = t >> 5;
    const int lid = t & 31;
    const int lr = lid >> 2;
    const int lc = lid & 3;
    const float SCL = 0.125f * 1.4426950408889634f;

    const size_t hb = ((size_t)(b * H_ + h)) << 16;
    const uint16_t* Qhg = g_Qh + hb;
    const uint16_t* Qlg = g_Ql + hb;
    const uint16_t* Khg = g_Kh + hb;
    const uint16_t* Klg = g_Kl + hb;
    const uint16_t* Vhg = g_Vh + hb;
    const uint16_t* Vlg = g_Vl + hb;
    const int* mrow = mask + b * S_;

    const uint32_t smb = (uint32_t)__cvta_generic_to_shared(sm);
    const int lrow8 = (lid & 7) + (lid & 8);
    const int lcol8 = (lid >> 4) << 3;

    {
        int row = t >> 1, half = (t & 1) * 32;
        size_t g = ((size_t)(q0 + row) << 6) + half;
        uint32_t so = (uint32_t)(row * RSTR + half) * 2;
        #pragma unroll
        for (int i = 0; i < 4; i++) {
            cp_async16(sm + SM_QH + so + i * 16, Qhg + g + i * 8);
            cp_async16(sm + SM_QL + so + i * 16, Qlg + g + i * 8);
        }
    }
    CP_ASYNC_COMMIT();

    auto load_kv = [&](int st, int kt) {
        int r = t >> 2, seg = t & 3;
        size_t g = ((size_t)(kt * 64 + r) << 6) + seg * 16;
        char* stb = sm + SM_KV + st * KV_STAGE;
        uint32_t so = (uint32_t)(r * RSTR + seg * 16) * 2;
        cp_async16(stb + OFF_KH + so,      Khg + g);
        cp_async16(stb + OFF_KH + so + 16, Khg + g + 8);
        cp_async16(stb + OFF_KL + so,      Klg + g);
        cp_async16(stb + OFF_KL + so + 16, Klg + g + 8);
        cp_async16(stb + OFF_VH + so,      Vhg + g);
        cp_async16(stb + OFF_VH + so + 16, Vhg + g + 8);
        cp_async16(stb + OFF_VL + so,      Vlg + g);
        cp_async16(stb + OFF_VL + so + 16, Vlg + g + 8);
        if (t < 16)
            cp_async16(sm + SM_MK + st * 256 + t * 16, mrow + kt * 64 + t * 4);
    };

    load_kv(0, 0);
    CP_ASYNC_COMMIT();

    float o[8][4];
    #pragma unroll
    for (int i = 0; i < 8; i++)
        #pragma unroll
        for (int j = 0; j < 4; j++) o[i][j] = 0.f;
    float m0 = -1.0e30f, m1 = -1.0e30f, l0 = 0.f, l1 = 0.f;

    const int gr0 = q0 + w * 16 + lr;
    const int ntiles = 2 * qb + 2;

    for (int kt = 0; kt < ntiles; kt++) {
        const int st = kt & 1;
        if (kt + 1 < ntiles) load_kv(st ^ 1, kt + 1);
        CP_ASYNC_COMMIT();
        CP_ASYNC_WAIT1();
        __syncthreads();

        const bool active = (kt * 64 <= q0 + w * 16 + 15);
        if (active) {
            const uint32_t kh32 = smb + SM_KV + st * KV_STAGE + OFF_KH;
            const uint32_t kl32 = smb + SM_KV + st * KV_STAGE + OFF_KL;
            const uint32_t vh32 = smb + SM_KV + st * KV_STAGE + OFF_VH;
            const uint32_t vl32 = smb + SM_KV + st * KV_STAGE + OFF_VL;
            const int* mk = (const int*)(sm + SM_MK + st * 256);

            int rem = q0 + w * 16 + 15 - kt * 64;
            if (rem > 63) rem = 63;
            const int nlim = (rem >> 4) + 1;

            float s[8][4];
            #pragma unroll
            for (int i = 0; i < 8; i++)
                #pragma unroll
                for (int j = 0; j < 4; j++) s[i][j] = 0.f;

            #pragma unroll
            for (int ks = 0; ks < 4; ks++) {
                const int ko = ks * 16;
                const uint32_t afo =
                    (uint32_t)((w * 16 + lrow8) * RSTR + ko + lcol8) * 2;
                uint32_t ah0, ah1, ah2, ah3, al0, al1, al2, al3;
                ldmatrix_x4(ah0, ah1, ah2, ah3, smb + SM_QH + afo);
                ldmatrix_x4(al0, al1, al2, al3, smb + SM_QL + afo);
                #pragma unroll
                for (int nfp = 0; nfp < 4; nfp++) {
                    if (nfp < nlim) {
                        const uint32_t bfo =
                            (uint32_t)((nfp * 16 + lrow8) * RSTR + ko + lcol8) * 2;
                        uint32_t bh0, bh1, bh2, bh3, bl0, bl1, bl2, bl3;
                        ldmatrix_x4(bh0, bh1, bh2, bh3, kh32 + bfo);
                        ldmatrix_x4(bl0, bl1, bl2, bl3, kl32 + bfo);
                        mma_bf16(s[2*nfp],   ah0, ah1, ah2, ah3, bh0, bh2);
                        mma_bf16(s[2*nfp],   ah0, ah1, ah2, ah3, bl0, bl2);
                        mma_bf16(s[2*nfp],   al0, al1, al2, al3, bh0, bh2);
                        mma_bf16(s[2*nfp+1], ah0, ah1, ah2, ah3, bh1, bh3);
                        mma_bf16(s[2*nfp+1], ah0, ah1, ah2, ah3, bl1, bl3);
                        mma_bf16(s[2*nfp+1], al0, al1, al2, al3, bh1, bh3);
                    }
                }
            }

            const bool diag = (kt >= 2 * qb);
            #pragma unroll
            for (int nf = 0; nf < 8; nf++) {
                int ci  = nf * 8 + 2 * lc;
                int c0  = kt * 64 + ci, c1 = c0 + 1;
                int mv0 = mk[ci], mv1 = mk[ci + 1];
                float v;
                v = s[nf][0] * SCL;
                if ((diag && c0 > gr0) || mv0 == 0) v = -1.0e30f;
                s[nf][0] = v;
                v = s[nf][1] * SCL;
                if ((diag && c1 > gr0) || mv1 == 0) v = -1.0e30f;
                s[nf][1] = v;
                v = s[nf][2] * SCL;
                if ((diag && c0 > gr0 + 8) || mv0 == 0) v = -1.0e30f;
                s[nf][2] = v;
                v = s[nf][3] * SCL;
                if ((diag && c1 > gr0 + 8) || mv1 == 0) v = -1.0e30f;
                s[nf][3] = v;
            }

            float mx0 = -1.0e30f, mx1 = -1.0e30f;
            #pragma unroll
            for (int nf = 0; nf < 8; nf++) {
                mx0 = fmaxf(mx0, fmaxf(s[nf][0], s[nf][1]));
                mx1 = fmaxf(mx1, fmaxf(s[nf][2], s[nf][3]));
            }
            mx0 = fmaxf(mx0, __shfl_xor_sync(0xffffffffu, mx0, 1));
            mx0 = fmaxf(mx0, __shfl_xor_sync(0xffffffffu, mx0, 2));
            mx1 = fmaxf(mx1, __shfl_xor_sync(0xffffffffu, mx1, 1));
            mx1 = fmaxf(mx1, __shfl_xor_sync(0xffffffffu, mx1, 2));
            float mn0 = fmaxf(m0, mx0), mn1 = fmaxf(m1, mx1);
            float alpha0 = exp2f(m0 - mn0), alpha1 = exp2f(m1 - mn1);
            m0 = mn0; m1 = mn1;

            float sum0 = 0.f, sum1 = 0.f;
            #pragma unroll
            for (int nf = 0; nf < 8; nf++) {
                float p;
                p = exp2f(s[nf][0] - mn0); s[nf][0] = p; sum0 += p;
                p = exp2f(s[nf][1] - mn0); s[nf][1] = p; sum0 += p;
                p = exp2f(s[nf][2] - mn1); s[nf][2] = p; sum1 += p;
                p = exp2f(s[nf][3] - mn1); s[nf][3] = p; sum1 += p;
            }
            sum0 += __shfl_xor_sync(0xffffffffu, sum0, 1);
            sum0 += __shfl_xor_sync(0xffffffffu, sum0, 2);
            sum1 += __shfl_xor_sync(0xffffffffu, sum1, 1);
            sum1 += __shfl_xor_sync(0xffffffffu, sum1, 2);
            l0 = l0 * alpha0 + sum0;
            l1 = l1 * alpha1 + sum1;

            #pragma unroll
            for (int nf = 0; nf < 8; nf++) {
                o[nf][0] *= alpha0; o[nf][1] *= alpha0;
                o[nf][2] *= alpha1; o[nf][3] *= alpha1;
            }

            const int g  = lid >> 3;
            const int lrow = lid & 7;
            #pragma unroll
            for (int ks = 0; ks < 4; ks++) {
                if (ks < nlim) {
                    uint32_t ph0 = packhi16(s[2*ks][0],   s[2*ks][1]);
                    uint32_t ph1 = packhi16(s[2*ks][2],   s[2*ks][3]);
                    uint32_t ph2 = packhi16(s[2*ks+1][0], s[2*ks+1][1]);
                    uint32_t ph3 = packhi16(s[2*ks+1][2], s[2*ks+1][3]);
                    uint32_t pl0 = packbf(trunclo(s[2*ks][0]),   trunclo(s[2*ks][1]));
                    uint32_t pl1 = packbf(trunclo(s[2*ks][2]),   trunclo(s[2*ks][3]));
                    uint32_t pl2 = packbf(trunclo(s[2*ks+1][0]), trunclo(s[2*ks+1][1]));
                    uint32_t pl3 = packbf(trunclo(s[2*ks+1][2]), trunclo(s[2*ks+1][3]));
                    #pragma unroll
                    for (int nfp = 0; nfp < 4; nfp++) {
                        uint32_t offB = (uint32_t)((ks * 16 + (g & 1) * 8 + lrow) * RSTR
                                                   + nfp * 16 + (g >> 1) * 8) * 2;
                        uint32_t bh0, bh1, bh2, bh3, bl0, bl1, bl2, bl3;
                        ldmatrix_x4_trans(bh0, bh1, bh2, bh3, vh32 + offB);
                        ldmatrix_x4_trans(bl0, bl1, bl2, bl3, vl32 + offB);
                        mma_bf16(o[2*nfp],   ph0, ph1, ph2, ph3, bh0, bh1);
                        mma_bf16(o[2*nfp],   ph0, ph1, ph2, ph3, bl0, bl1);
                        mma_bf16(o[2*nfp],   pl0, pl1, pl2, pl3, bh0, bh1);
                        mma_bf16(o[2*nfp+1], ph0, ph1, ph2, ph3, bh2, bh3);
                        mma_bf16(o[2*nfp+1], ph0, ph1, ph2, ph3, bl2, bl3);
                        mma_bf16(o[2*nfp+1], pl0, pl1, pl2, pl3, bh2, bh3);
                    }
                }
            }
        }
        __syncthreads();
    }

    float inv0 = 1.0f / l0, inv1 = 1.0f / l1;
    #pragma unroll
    for (int nf = 0; nf < 8; nf++) {
        int col = h * DK_ + nf * 8 + 2 * lc;
        float2 r0, r1;
        r0.x = o[nf][0] * inv0; r0.y = o[nf][1] * inv0;
        r1.x = o[nf][2] * inv1; r1.y = o[nf][3] * inv1;
        *(float2*)&out[(size_t)(b * S_ + gr0) * D_ + col] = r0;
        *(float2*)&out[(size_t)(b * S_ + gr0 + 8) * D_ + col] = r1;
    }
}

// ---------------------------------------------------------------------------
// Launch
// inputs: query, key, value, att_mask, Wq, bq, Wk, bk, Wv, bv
// ---------------------------------------------------------------------------
extern "C" void kernel_launch(void* const* d_in, const int* in_sizes, int n_in,
                              void* d_out, int out_size) {
    (void)in_sizes; (void)n_in; (void)out_size;
    const float* query = (const float*)d_in[0];
    const float* key   = (const float*)d_in[1];
    const float* value = (const float*)d_in[2];
    const int*   amask = (const int*)  d_in[3];
    const float* Wq = (const float*)d_in[4];
    const float* bq = (const float*)d_in[5];
    const float* Wk = (const float*)d_in[6];
    const float* bk = (const float*)d_in[7];
    const float* Wv = (const float*)d_in[8];
    const float* bv = (const float*)d_in[9];
    float* out = (float*)d_out;

    static uint16_t *x16 = nullptr, *w16 = nullptr;
    if (!x16) {
        cudaGetSymbolAddress((void**)&x16, g_X16);
        cudaGetSymbolAddress((void**)&w16, g_W16);
        cudaFuncSetAttribute(attn_mma,
                             cudaFuncAttributeMaxDynamicSharedMemorySize, ATTN_SMEM);
    }

    const int NX4 = M_TOT * D_ / 4;   // 1048576
    const int NW4 = D_ * D_ / 4;      // 262144
    dim3 gx((NX4 + 255) / 256, 1, 3);
    cvt_f16_kernel<<<gx, 256>>>(query, key, value, x16, NX4);
    dim3 gw((NW4 + 255) / 256, 1, 3);
    cvt_f16_kernel<<<gw, 256>>>(Wq, Wk, Wv, w16, NW4);

    dim3 gproj(D_ / PBN, M_TOT / PBM, 3);   // (8, 32, 3)
    qkv_proj_mma<<<gproj, 256>>>(bq, bk, bv);

    dim3 gattn(S_ / 128, H_, B_);            // (8, 16, 4)
    attn_mma<<<gattn, 256, ATTN_SMEM>>>(amask, out);
}

// round 13
// speedup vs baseline: 1.8530x; 1.3839x over previous
#include <cuda_runtime.h>
#include <cuda_bf16.h>
#include <cuda_fp16.h>
#include <cstdint>

// Problem constants
#define B_ 4
#define S_ 1024
#define D_ 1024
#define H_ 16
#define DK_ 64
#define M_TOT (B_ * S_)   // 4096

// Q/K/V in fp16, head-major: [(b*H+h)][s][64], 64-elem rows (128B).
__device__ uint16_t g_Q16[B_ * H_ * S_ * DK_];
__device__ uint16_t g_K16[B_ * H_ * S_ * DK_];
__device__ uint16_t g_V16[B_ * H_ * S_ * DK_];
// fp16-pre-converted projection inputs
__device__ uint16_t g_X16[3 * M_TOT * D_];
__device__ uint16_t g_W16[3 * D_ * D_];

// ---------------------------------------------------------------------------
// PTX helpers (baseline sm_80+ features only — target is sm_100 BASE).
// ---------------------------------------------------------------------------
__device__ __forceinline__ void cp_async16(void* smem_dst, const void* gmem_src) {
    uint32_t d = (uint32_t)__cvta_generic_to_shared(smem_dst);
    asm volatile("cp.async.ca.shared.global [%0], [%1], 16;"
                 :: "r"(d), "l"(gmem_src) : "memory");
}
#define CP_ASYNC_COMMIT() asm volatile("cp.async.commit_group;" ::: "memory")
#define CP_ASYNC_WAIT1()  asm volatile("cp.async.wait_group 1;" ::: "memory")

// fp16 m16n8k16, fp32 accumulate
__device__ __forceinline__ void mma_f16(float c[4],
                                        uint32_t a0, uint32_t a1, uint32_t a2, uint32_t a3,
                                        uint32_t b0, uint32_t b1) {
    asm volatile(
        "mma.sync.aligned.m16n8k16.row.col.f32.f16.f16.f32 "
        "{%0,%1,%2,%3}, {%4,%5,%6,%7}, {%8,%9}, {%0,%1,%2,%3};"
        : "+f"(c[0]), "+f"(c[1]), "+f"(c[2]), "+f"(c[3])
        : "r"(a0), "r"(a1), "r"(a2), "r"(a3), "r"(b0), "r"(b1));
}
__device__ __forceinline__ void ldmatrix_x4(uint32_t& r0, uint32_t& r1,
                                            uint32_t& r2, uint32_t& r3,
                                            uint32_t smem_addr) {
    asm volatile("ldmatrix.sync.aligned.m8n8.x4.shared.b16 "
                 "{%0,%1,%2,%3}, [%4];"
                 : "=r"(r0), "=r"(r1), "=r"(r2), "=r"(r3) : "r"(smem_addr));
}
__device__ __forceinline__ void ldmatrix_x4_trans(uint32_t& r0, uint32_t& r1,
                                                  uint32_t& r2, uint32_t& r3,
                                                  uint32_t smem_addr) {
    asm volatile("ldmatrix.sync.aligned.m8n8.x4.trans.shared.b16 "
                 "{%0,%1,%2,%3}, [%4];"
                 : "=r"(r0), "=r"(r1), "=r"(r2), "=r"(r3) : "r"(smem_addr));
}
__device__ __forceinline__ uint32_t packhf(float a, float b) {
    __half2 t = __floats2half2_rn(a, b);
    return *reinterpret_cast<uint32_t*>(&t);
}

// head-major index for proj epilogue stores
#define QKV_IDX(row, col) \
    ((((size_t)((row) >> 10) * H_ + ((col) >> 6)) << 16) + \
     (((size_t)((row) & 1023)) << 6) + ((col) & 63))

// ---------------------------------------------------------------------------
// Pre-pass: fp32 -> fp16, float4-vectorized, z picks tensor.
// ---------------------------------------------------------------------------
__global__ void cvt_f16_kernel(const float* __restrict__ a,
                               const float* __restrict__ b,
                               const float* __restrict__ c,
                               uint16_t* __restrict__ out, int n4) {
    int i = blockIdx.x * blockDim.x + threadIdx.x;
    if (i >= n4) return;
    const float* src = (blockIdx.z == 0) ? a : (blockIdx.z == 1) ? b : c;
    float4 v = ((const float4*)src)[i];
    uint2 r;
    r.x = packhf(v.x, v.y);
    r.y = packhf(v.z, v.w);
    ((uint2*)(out + (size_t)blockIdx.z * n4 * 4))[i] = r;
}

// ---------------------------------------------------------------------------
// Projection GEMM via fp16 m16n8k16. 2-stage cp.async, PBK=32.
// Epilogue emits fp16 head-major.
// ---------------------------------------------------------------------------
#define PBM 128
#define PBN 128
#define PBK 32
#define PROW 40                     // ushort row stride (80B) — conflict-free
#define KSTEPS (D_ / PBK)           // 32
#define P_A_USH (PBM * PROW)        // 5120 ushorts per A tile

__global__ __launch_bounds__(256, 2)
void qkv_proj_mma(const float* __restrict__ bq,
                  const float* __restrict__ bk,
                  const float* __restrict__ bv) {
    __shared__ uint16_t As[2][P_A_USH];
    __shared__ uint16_t Bs[2][P_A_USH];

    const int z = blockIdx.z;
    const uint16_t* X = g_X16 + (size_t)z * M_TOT * D_;
    const uint16_t* W = g_W16 + (size_t)z * D_ * D_;
    const float* bias = (z == 0) ? bq : (z == 1) ? bk : bv;
    uint16_t* Out = (z == 0) ? g_Q16 : (z == 1) ? g_K16 : g_V16;

    const int t   = threadIdx.x;
    const int wid = t >> 5;
    const int lid = t & 31;
    const int lr  = lid >> 2;
    const int lc  = lid & 3;
    const int wm  = wid & 1;
    const int wn  = wid >> 1;
    const int m0  = blockIdx.y * PBM;
    const int n0  = blockIdx.x * PBN;

    const int lrow8 = (lid & 7) + (lid & 8);          // 0..15
    const int lcol8 = (lid >> 4) << 3;                // 0 or 8

    float acc[4][4][4];
    #pragma unroll
    for (int i = 0; i < 4; i++)
        #pragma unroll
        for (int j = 0; j < 4; j++)
            #pragma unroll
            for (int r = 0; r < 4; r++) acc[i][j][r] = 0.f;

    auto load_stage = [&](int s, int ks) {
        const int k0 = ks * PBK;
        #pragma unroll
        for (int i = 0; i < 2; i++) {
            int job = t + i * 256;          // 0..511
            int row = job >> 2;             // 0..127
            int ch  = (job & 3) * 8;        // ushort offset 0,8,16,24
            cp_async16(&As[s][row * PROW + ch], &X[(size_t)(m0 + row) * D_ + k0 + ch]);
            cp_async16(&Bs[s][row * PROW + ch], &W[(size_t)(n0 + row) * D_ + k0 + ch]);
        }
    };

    load_stage(0, 0);
    CP_ASYNC_COMMIT();

    for (int ks = 0; ks < KSTEPS; ks++) {
        const int s = ks & 1;
        if (ks + 1 < KSTEPS) load_stage(s ^ 1, ks + 1);
        CP_ASYNC_COMMIT();
        CP_ASYNC_WAIT1();
        __syncthreads();

        #pragma unroll
        for (int kh = 0; kh < 2; kh++) {
            const int ko = kh * 16;
            uint32_t a[4][4], b[4][2];
            #pragma unroll
            for (int mf = 0; mf < 4; mf++) {
                uint32_t ad = (uint32_t)__cvta_generic_to_shared(
                    &As[s][(wm * 64 + mf * 16 + lrow8) * PROW + ko + lcol8]);
                ldmatrix_x4(a[mf][0], a[mf][1], a[mf][2], a[mf][3], ad);
            }
            #pragma unroll
            for (int np = 0; np < 2; np++) {
                uint32_t bd = (uint32_t)__cvta_generic_to_shared(
                    &Bs[s][(wn * 32 + np * 16 + lrow8) * PROW + ko + lcol8]);
                uint32_t b0, b1, b2, b3;
                ldmatrix_x4(b0, b1, b2, b3, bd);
                b[2 * np][0] = b0; b[2 * np][1] = b2;
                b[2 * np + 1][0] = b1; b[2 * np + 1][1] = b3;
            }
            #pragma unroll
            for (int mf = 0; mf < 4; mf++)
                #pragma unroll
                for (int nf = 0; nf < 4; nf++)
                    mma_f16(acc[mf][nf], a[mf][0], a[mf][1], a[mf][2], a[mf][3],
                            b[nf][0], b[nf][1]);
        }
        __syncthreads();
    }

    // Epilogue: bias add, store fp16 head-major.
    #pragma unroll
    for (int mf = 0; mf < 4; mf++) {
        int row = m0 + wm * 64 + mf * 16 + lr;
        #pragma unroll
        for (int nf = 0; nf < 4; nf++) {
            int col = n0 + wn * 32 + nf * 8 + lc * 2;
            float2 bv2 = *(const float2*)&bias[col];
            float v00 = acc[mf][nf][0] + bv2.x;
            float v01 = acc[mf][nf][1] + bv2.y;
            float v10 = acc[mf][nf][2] + bv2.x;
            float v11 = acc[mf][nf][3] + bv2.y;
            *(uint32_t*)&Out[QKV_IDX(row, col)]     = packhf(v00, v01);
            *(uint32_t*)&Out[QKV_IDX(row + 8, col)] = packhf(v10, v11);
        }
    }
}

// ---------------------------------------------------------------------------
// Flash attention, single-pass fp16 MMA, log2-domain softmax.
// CTA: 128 q-rows x head; 8 warps, warp-local softmax; K-tiles of 64.
// cp.async double-buffered K/V; all fragments via ldmatrix.
// ---------------------------------------------------------------------------
#define RSTR 72                       // row stride in ushorts (144B)
#define SM_Q  0
#define SM_KV 18432                   // 2 stages of {K, V}
#define KV_STAGE 18432
#define OFF_K 0
#define OFF_V 9216
#define SM_MK (SM_KV + 2 * KV_STAGE)  // 55296; 2 x 256B mask stages
#define ATTN_SMEM (SM_MK + 512)       // 55808

__global__ __launch_bounds__(256, 2)
void attn_mma(const int* __restrict__ mask, float* __restrict__ out) {
    extern __shared__ char sm[];

    const int qb = (int)(gridDim.x - 1) - (int)blockIdx.x;   // heavy blocks first
    const int h  = blockIdx.y;
    const int b  = blockIdx.z;
    const int q0 = qb * 128;
    const int t  = threadIdx.x;
    const int w  = t >> 5;
    const int lid = t & 31;
    const int lr = lid >> 2;
    const int lc = lid & 3;
    const float SCL = 0.125f * 1.4426950408889634f;

    const size_t hb = ((size_t)(b * H_ + h)) << 16;
    const uint16_t* Qg = g_Q16 + hb;
    const uint16_t* Kg = g_K16 + hb;
    const uint16_t* Vg = g_V16 + hb;
    const int* mrow = mask + b * S_;

    const uint32_t smb = (uint32_t)__cvta_generic_to_shared(sm);
    const int lrow8 = (lid & 7) + (lid & 8);
    const int lcol8 = (lid >> 4) << 3;

    // ---- prologue: Q tile (group 0), first K/V tile (group 1) ----
    {
        int row = t >> 1, half = (t & 1) * 32;
        size_t g = ((size_t)(q0 + row) << 6) + half;
        uint32_t so = (uint32_t)(row * RSTR + half) * 2;
        #pragma unroll
        for (int i = 0; i < 4; i++)
            cp_async16(sm + SM_Q + so + i * 16, Qg + g + i * 8);
    }
    CP_ASYNC_COMMIT();

    auto load_kv = [&](int st, int kt) {
        int r = t >> 2, seg = t & 3;
        size_t g = ((size_t)(kt * 64 + r) << 6) + seg * 16;
        char* stb = sm + SM_KV + st * KV_STAGE;
        uint32_t so = (uint32_t)(r * RSTR + seg * 16) * 2;
        cp_async16(stb + OFF_K + so,      Kg + g);
        cp_async16(stb + OFF_K + so + 16, Kg + g + 8);
        cp_async16(stb + OFF_V + so,      Vg + g);
        cp_async16(stb + OFF_V + so + 16, Vg + g + 8);
        if (t < 16)
            cp_async16(sm + SM_MK + st * 256 + t * 16, mrow + kt * 64 + t * 4);
    };

    load_kv(0, 0);
    CP_ASYNC_COMMIT();

    float o[8][4];
    #pragma unroll
    for (int i = 0; i < 8; i++)
        #pragma unroll
        for (int j = 0; j < 4; j++) o[i][j] = 0.f;
    float m0 = -1.0e30f, m1 = -1.0e30f, l0 = 0.f, l1 = 0.f;

    const int gr0 = q0 + w * 16 + lr;
    const int ntiles = 2 * qb + 2;

    for (int kt = 0; kt < ntiles; kt++) {
        const int st = kt & 1;
        if (kt + 1 < ntiles) load_kv(st ^ 1, kt + 1);
        CP_ASYNC_COMMIT();
        CP_ASYNC_WAIT1();
        __syncthreads();

        const bool active = (kt * 64 <= q0 + w * 16 + 15);
        if (active) {
            const uint32_t k32 = smb + SM_KV + st * KV_STAGE + OFF_K;
            const uint32_t v32 = smb + SM_KV + st * KV_STAGE + OFF_V;
            const int* mk = (const int*)(sm + SM_MK + st * 256);

            int rem = q0 + w * 16 + 15 - kt * 64;
            if (rem > 63) rem = 63;
            const int nlim = (rem >> 4) + 1;          // 1..4

            // ---- S = Q K^T (single-pass fp16) ----
            float s[8][4];
            #pragma unroll
            for (int i = 0; i < 8; i++)
                #pragma unroll
                for (int j = 0; j < 4; j++) s[i][j] = 0.f;

            #pragma unroll
            for (int ks = 0; ks < 4; ks++) {
                const int ko = ks * 16;
                const uint32_t afo =
                    (uint32_t)((w * 16 + lrow8) * RSTR + ko + lcol8) * 2;
                uint32_t a0, a1, a2, a3;
                ldmatrix_x4(a0, a1, a2, a3, smb + SM_Q + afo);
                #pragma unroll
                for (int nfp = 0; nfp < 4; nfp++) {
                    if (nfp < nlim) {
                        const uint32_t bfo =
                            (uint32_t)((nfp * 16 + lrow8) * RSTR + ko + lcol8) * 2;
                        uint32_t b0, b1, b2, b3;
                        ldmatrix_x4(b0, b1, b2, b3, k32 + bfo);
                        mma_f16(s[2*nfp],   a0, a1, a2, a3, b0, b2);
                        mma_f16(s[2*nfp+1], a0, a1, a2, a3, b1, b3);
                    }
                }
            }

            // ---- scale (log2 domain) + mask ----
            const bool diag = (kt >= 2 * qb);
            #pragma unroll
            for (int nf = 0; nf < 8; nf++) {
                int ci  = nf * 8 + 2 * lc;
                int c0  = kt * 64 + ci, c1 = c0 + 1;
                int mv0 = mk[ci], mv1 = mk[ci + 1];
                float v;
                v = s[nf][0] * SCL;
                if ((diag && c0 > gr0) || mv0 == 0) v = -1.0e30f;
                s[nf][0] = v;
                v = s[nf][1] * SCL;
                if ((diag && c1 > gr0) || mv1 == 0) v = -1.0e30f;
                s[nf][1] = v;
                v = s[nf][2] * SCL;
                if ((diag && c0 > gr0 + 8) || mv0 == 0) v = -1.0e30f;
                s[nf][2] = v;
                v = s[nf][3] * SCL;
                if ((diag && c1 > gr0 + 8) || mv1 == 0) v = -1.0e30f;
                s[nf][3] = v;
            }

            // ---- online softmax (warp-local, exp2 domain) ----
            float mx0 = -1.0e30f, mx1 = -1.0e30f;
            #pragma unroll
            for (int nf = 0; nf < 8; nf++) {
                mx0 = fmaxf(mx0, fmaxf(s[nf][0], s[nf][1]));
                mx1 = fmaxf(mx1, fmaxf(s[nf][2], s[nf][3]));
            }
            mx0 = fmaxf(mx0, __shfl_xor_sync(0xffffffffu, mx0, 1));
            mx0 = fmaxf(mx0, __shfl_xor_sync(0xffffffffu, mx0, 2));
            mx1 = fmaxf(mx1, __shfl_xor_sync(0xffffffffu, mx1, 1));
            mx1 = fmaxf(mx1, __shfl_xor_sync(0xffffffffu, mx1, 2));
            float mn0 = fmaxf(m0, mx0), mn1 = fmaxf(m1, mx1);
            float alpha0 = exp2f(m0 - mn0), alpha1 = exp2f(m1 - mn1);
            m0 = mn0; m1 = mn1;

            float sum0 = 0.f, sum1 = 0.f;
            #pragma unroll
            for (int nf = 0; nf < 8; nf++) {
                float p;
                p = exp2f(s[nf][0] - mn0); s[nf][0] = p; sum0 += p;
                p = exp2f(s[nf][1] - mn0); s[nf][1] = p; sum0 += p;
                p = exp2f(s[nf][2] - mn1); s[nf][2] = p; sum1 += p;
                p = exp2f(s[nf][3] - mn1); s[nf][3] = p; sum1 += p;
            }
            sum0 += __shfl_xor_sync(0xffffffffu, sum0, 1);
            sum0 += __shfl_xor_sync(0xffffffffu, sum0, 2);
            sum1 += __shfl_xor_sync(0xffffffffu, sum1, 1);
            sum1 += __shfl_xor_sync(0xffffffffu, sum1, 2);
            l0 = l0 * alpha0 + sum0;
            l1 = l1 * alpha1 + sum1;

            #pragma unroll
            for (int nf = 0; nf < 8; nf++) {
                o[nf][0] *= alpha0; o[nf][1] *= alpha0;
                o[nf][2] *= alpha1; o[nf][3] *= alpha1;
            }

            // ---- O += P V (single-pass fp16) ----
            const int g  = lid >> 3;
            const int lrow = lid & 7;
            #pragma unroll
            for (int ks = 0; ks < 4; ks++) {
                if (ks < nlim) {
                    uint32_t p0 = packhf(s[2*ks][0],   s[2*ks][1]);
                    uint32_t p1 = packhf(s[2*ks][2],   s[2*ks][3]);
                    uint32_t p2 = packhf(s[2*ks+1][0], s[2*ks+1][1]);
                    uint32_t p3 = packhf(s[2*ks+1][2], s[2*ks+1][3]);
                    #pragma unroll
                    for (int nfp = 0; nfp < 4; nfp++) {
                        uint32_t offB = (uint32_t)((ks * 16 + (g & 1) * 8 + lrow) * RSTR
                                                   + nfp * 16 + (g >> 1) * 8) * 2;
                        uint32_t b0, b1, b2, b3;
                        ldmatrix_x4_trans(b0, b1, b2, b3, v32 + offB);
                        mma_f16(o[2*nfp],   p0, p1, p2, p3, b0, b1);
                        mma_f16(o[2*nfp+1], p0, p1, p2, p3, b2, b3);
                    }
                }
            }
        }
        __syncthreads();
    }

    // ---- epilogue: normalize + store (fp32) ----
    float inv0 = 1.0f / l0, inv1 = 1.0f / l1;
    #pragma unroll
    for (int nf = 0; nf < 8; nf++) {
        int col = h * DK_ + nf * 8 + 2 * lc;
        float2 r0, r1;
        r0.x = o[nf][0] * inv0; r0.y = o[nf][1] * inv0;
        r1.x = o[nf][2] * inv1; r1.y = o[nf][3] * inv1;
        *(float2*)&out[(size_t)(b * S_ + gr0) * D_ + col] = r0;
        *(float2*)&out[(size_t)(b * S_ + gr0 + 8) * D_ + col] = r1;
    }
}

// ---------------------------------------------------------------------------
// Launch
// inputs: query, key, value, att_mask, Wq, bq, Wk, bk, Wv, bv
// ---------------------------------------------------------------------------
extern "C" void kernel_launch(void* const* d_in, const int* in_sizes, int n_in,
                              void* d_out, int out_size) {
    (void)in_sizes; (void)n_in; (void)out_size;
    const float* query = (const float*)d_in[0];
    const float* key   = (const float*)d_in[1];
    const float* value = (const float*)d_in[2];
    const int*   amask = (const int*)  d_in[3];
    const float* Wq = (const float*)d_in[4];
    const float* bq = (const float*)d_in[5];
    const float* Wk = (const float*)d_in[6];
    const float* bk = (const float*)d_in[7];
    const float* Wv = (const float*)d_in[8];
    const float* bv = (const float*)d_in[9];
    float* out = (float*)d_out;

    static uint16_t *x16 = nullptr, *w16 = nullptr;
    if (!x16) {
        cudaGetSymbolAddress((void**)&x16, g_X16);
        cudaGetSymbolAddress((void**)&w16, g_W16);
        cudaFuncSetAttribute(attn_mma,
                             cudaFuncAttributeMaxDynamicSharedMemorySize, ATTN_SMEM);
    }

    const int NX4 = M_TOT * D_ / 4;   // 1048576
    const int NW4 = D_ * D_ / 4;      // 262144
    dim3 gx((NX4 + 255) / 256, 1, 3);
    cvt_f16_kernel<<<gx, 256>>>(query, key, value, x16, NX4);
    dim3 gw((NW4 + 255) / 256, 1, 3);
    cvt_f16_kernel<<<gw, 256>>>(Wq, Wk, Wv, w16, NW4);

    dim3 gproj(D_ / PBN, M_TOT / PBM, 3);   // (8, 32, 3)
    qkv_proj_mma<<<gproj, 256>>>(bq, bk, bv);

    dim3 gattn(S_ / 128, H_, B_);            // (8, 16, 4)
    attn_mma<<<gattn, 256, ATTN_SMEM>>>(amask, out);
}

// round 14
// speedup vs baseline: 1.8958x; 1.0231x over previous
#include <cuda_runtime.h>
#include <cuda_bf16.h>
#include <cuda_fp16.h>
#include <cstdint>

// Problem constants
#define B_ 4
#define S_ 1024
#define D_ 1024
#define H_ 16
#define DK_ 64
#define M_TOT (B_ * S_)   // 4096

// Q/K/V in fp16, head-major: [(b*H+h)][s][64], 64-elem rows (128B).
// Q is pre-scaled by 0.125*log2(e) so attention softmax runs in exp2 domain
// with no per-element scaling.
__device__ uint16_t g_Q16[B_ * H_ * S_ * DK_];
__device__ uint16_t g_K16[B_ * H_ * S_ * DK_];
__device__ uint16_t g_V16[B_ * H_ * S_ * DK_];
// fp16-pre-converted projection inputs
__device__ uint16_t g_X16[3 * M_TOT * D_];
__device__ uint16_t g_W16[3 * D_ * D_];
// per-64-column-block mask validity flags: [b][blk] (1 = all 64 cols valid)
__device__ int g_mflag[B_ * (S_ / 64)];

#define SCL_Q 0.18033688011112042f   // 0.125 * log2(e)

// ---------------------------------------------------------------------------
// PTX helpers (baseline sm_80+ features only — target is sm_100 BASE).
// ---------------------------------------------------------------------------
__device__ __forceinline__ void cp_async16(void* smem_dst, const void* gmem_src) {
    uint32_t d = (uint32_t)__cvta_generic_to_shared(smem_dst);
    asm volatile("cp.async.ca.shared.global [%0], [%1], 16;"
                 :: "r"(d), "l"(gmem_src) : "memory");
}
#define CP_ASYNC_COMMIT() asm volatile("cp.async.commit_group;" ::: "memory")
#define CP_ASYNC_WAIT1()  asm volatile("cp.async.wait_group 1;" ::: "memory")

// fp16 m16n8k16, fp32 accumulate
__device__ __forceinline__ void mma_f16(float c[4],
                                        uint32_t a0, uint32_t a1, uint32_t a2, uint32_t a3,
                                        uint32_t b0, uint32_t b1) {
    asm volatile(
        "mma.sync.aligned.m16n8k16.row.col.f32.f16.f16.f32 "
        "{%0,%1,%2,%3}, {%4,%5,%6,%7}, {%8,%9}, {%0,%1,%2,%3};"
        : "+f"(c[0]), "+f"(c[1]), "+f"(c[2]), "+f"(c[3])
        : "r"(a0), "r"(a1), "r"(a2), "r"(a3), "r"(b0), "r"(b1));
}
__device__ __forceinline__ void ldmatrix_x4(uint32_t& r0, uint32_t& r1,
                                            uint32_t& r2, uint32_t& r3,
                                            uint32_t smem_addr) {
    asm volatile("ldmatrix.sync.aligned.m8n8.x4.shared.b16 "
                 "{%0,%1,%2,%3}, [%4];"
                 : "=r"(r0), "=r"(r1), "=r"(r2), "=r"(r3) : "r"(smem_addr));
}
__device__ __forceinline__ void ldmatrix_x4_trans(uint32_t& r0, uint32_t& r1,
                                                  uint32_t& r2, uint32_t& r3,
                                                  uint32_t smem_addr) {
    asm volatile("ldmatrix.sync.aligned.m8n8.x4.trans.shared.b16 "
                 "{%0,%1,%2,%3}, [%4];"
                 : "=r"(r0), "=r"(r1), "=r"(r2), "=r"(r3) : "r"(smem_addr));
}
__device__ __forceinline__ uint32_t packhf(float a, float b) {
    __half2 t = __floats2half2_rn(a, b);
    return *reinterpret_cast<uint32_t*>(&t);
}

// head-major index for proj epilogue stores
#define QKV_IDX(row, col) \
    ((((size_t)((row) >> 10) * H_ + ((col) >> 6)) << 16) + \
     (((size_t)((row) & 1023)) << 6) + ((col) & 63))

// ---------------------------------------------------------------------------
// Pre-pass: fp32 -> fp16, float4-vectorized, z picks tensor.
// ---------------------------------------------------------------------------
__global__ void cvt_f16_kernel(const float* __restrict__ a,
                               const float* __restrict__ b,
                               const float* __restrict__ c,
                               uint16_t* __restrict__ out, int n4) {
    int i = blockIdx.x * blockDim.x + threadIdx.x;
    if (i >= n4) return;
    const float* src = (blockIdx.z == 0) ? a : (blockIdx.z == 1) ? b : c;
    float4 v = ((const float4*)src)[i];
    uint2 r;
    r.x = packhf(v.x, v.y);
    r.y = packhf(v.z, v.w);
    ((uint2*)(out + (size_t)blockIdx.z * n4 * 4))[i] = r;
}

// ---------------------------------------------------------------------------
// Pre-pass: mask -> per-64-col-block validity flag. One thread per block.
// ---------------------------------------------------------------------------
__global__ void mask_flags_kernel(const int* __restrict__ mask) {
    int i = threadIdx.x;                 // 0..63  -> (b, blk)
    if (i >= B_ * (S_ / 64)) return;
    const int* m = mask + (i >> 4) * S_ + (i & 15) * 64;
    int all = 1;
    #pragma unroll 8
    for (int j = 0; j < 64; j++) all &= (m[j] != 0);
    g_mflag[i] = all;
}

// ---------------------------------------------------------------------------
// Projection GEMM via fp16 m16n8k16. 2-stage cp.async, PBK=32.
// Epilogue emits fp16 head-major; Q output pre-scaled by SCL_Q.
// ---------------------------------------------------------------------------
#define PBM 128
#define PBN 128
#define PBK 32
#define PROW 40                     // ushort row stride (80B) — conflict-free
#define KSTEPS (D_ / PBK)           // 32
#define P_A_USH (PBM * PROW)        // 5120 ushorts per A tile

__global__ __launch_bounds__(256, 2)
void qkv_proj_mma(const float* __restrict__ bq,
                  const float* __restrict__ bk,
                  const float* __restrict__ bv) {
    __shared__ uint16_t As[2][P_A_USH];
    __shared__ uint16_t Bs[2][P_A_USH];

    const int z = blockIdx.z;
    const uint16_t* X = g_X16 + (size_t)z * M_TOT * D_;
    const uint16_t* W = g_W16 + (size_t)z * D_ * D_;
    const float* bias = (z == 0) ? bq : (z == 1) ? bk : bv;
    uint16_t* Out = (z == 0) ? g_Q16 : (z == 1) ? g_K16 : g_V16;
    const float oscale = (z == 0) ? SCL_Q : 1.0f;

    const int t   = threadIdx.x;
    const int wid = t >> 5;
    const int lid = t & 31;
    const int lr  = lid >> 2;
    const int lc  = lid & 3;
    const int wm  = wid & 1;
    const int wn  = wid >> 1;
    const int m0  = blockIdx.y * PBM;
    const int n0  = blockIdx.x * PBN;

    const int lrow8 = (lid & 7) + (lid & 8);          // 0..15
    const int lcol8 = (lid >> 4) << 3;                // 0 or 8

    float acc[4][4][4];
    #pragma unroll
    for (int i = 0; i < 4; i++)
        #pragma unroll
        for (int j = 0; j < 4; j++)
            #pragma unroll
            for (int r = 0; r < 4; r++) acc[i][j][r] = 0.f;

    auto load_stage = [&](int s, int ks) {
        const int k0 = ks * PBK;
        #pragma unroll
        for (int i = 0; i < 2; i++) {
            int job = t + i * 256;          // 0..511
            int row = job >> 2;             // 0..127
            int ch  = (job & 3) * 8;        // ushort offset 0,8,16,24
            cp_async16(&As[s][row * PROW + ch], &X[(size_t)(m0 + row) * D_ + k0 + ch]);
            cp_async16(&Bs[s][row * PROW + ch], &W[(size_t)(n0 + row) * D_ + k0 + ch]);
        }
    };

    load_stage(0, 0);
    CP_ASYNC_COMMIT();

    for (int ks = 0; ks < KSTEPS; ks++) {
        const int s = ks & 1;
        if (ks + 1 < KSTEPS) load_stage(s ^ 1, ks + 1);
        CP_ASYNC_COMMIT();
        CP_ASYNC_WAIT1();
        __syncthreads();

        #pragma unroll
        for (int kh = 0; kh < 2; kh++) {
            const int ko = kh * 16;
            uint32_t a[4][4], b[4][2];
            #pragma unroll
            for (int mf = 0; mf < 4; mf++) {
                uint32_t ad = (uint32_t)__cvta_generic_to_shared(
                    &As[s][(wm * 64 + mf * 16 + lrow8) * PROW + ko + lcol8]);
                ldmatrix_x4(a[mf][0], a[mf][1], a[mf][2], a[mf][3], ad);
            }
            #pragma unroll
            for (int np = 0; np < 2; np++) {
                uint32_t bd = (uint32_t)__cvta_generic_to_shared(
                    &Bs[s][(wn * 32 + np * 16 + lrow8) * PROW + ko + lcol8]);
                uint32_t b0, b1, b2, b3;
                ldmatrix_x4(b0, b1, b2, b3, bd);
                b[2 * np][0] = b0; b[2 * np][1] = b2;
                b[2 * np + 1][0] = b1; b[2 * np + 1][1] = b3;
            }
            #pragma unroll
            for (int mf = 0; mf < 4; mf++)
                #pragma unroll
                for (int nf = 0; nf < 4; nf++)
                    mma_f16(acc[mf][nf], a[mf][0], a[mf][1], a[mf][2], a[mf][3],
                            b[nf][0], b[nf][1]);
        }
        __syncthreads();
    }

    // Epilogue: bias add (+ Q pre-scale), store fp16 head-major.
    #pragma unroll
    for (int mf = 0; mf < 4; mf++) {
        int row = m0 + wm * 64 + mf * 16 + lr;
        #pragma unroll
        for (int nf = 0; nf < 4; nf++) {
            int col = n0 + wn * 32 + nf * 8 + lc * 2;
            float2 bv2 = *(const float2*)&bias[col];
            float v00 = (acc[mf][nf][0] + bv2.x) * oscale;
            float v01 = (acc[mf][nf][1] + bv2.y) * oscale;
            float v10 = (acc[mf][nf][2] + bv2.x) * oscale;
            float v11 = (acc[mf][nf][3] + bv2.y) * oscale;
            *(uint32_t*)&Out[QKV_IDX(row, col)]     = packhf(v00, v01);
            *(uint32_t*)&Out[QKV_IDX(row + 8, col)] = packhf(v10, v11);
        }
    }
}

// ---------------------------------------------------------------------------
// Flash attention, single-pass fp16 MMA, exp2-domain softmax (Q pre-scaled).
// Per-tile mask fast path via g_mflag: non-diag valid tiles do ZERO mask work.
// ---------------------------------------------------------------------------
#define RSTR 72                       // row stride in ushorts (144B)
#define SM_Q  0
#define SM_KV 18432                   // 2 stages of {K, V}
#define KV_STAGE 18432
#define OFF_K 0
#define OFF_V 9216
#define SM_MK (SM_KV + 2 * KV_STAGE)  // 55296; 2 x 256B mask stages
#define ATTN_SMEM (SM_MK + 512)       // 55808

__global__ __launch_bounds__(256, 2)
void attn_mma(const int* __restrict__ mask, float* __restrict__ out) {
    extern __shared__ char sm[];

    const int qb = (int)(gridDim.x - 1) - (int)blockIdx.x;   // heavy blocks first
    const int h  = blockIdx.y;
    const int b  = blockIdx.z;
    const int q0 = qb * 128;
    const int t  = threadIdx.x;
    const int w  = t >> 5;
    const int lid = t & 31;
    const int lr = lid >> 2;
    const int lc = lid & 3;

    const size_t hb = ((size_t)(b * H_ + h)) << 16;
    const uint16_t* Qg = g_Q16 + hb;
    const uint16_t* Kg = g_K16 + hb;
    const uint16_t* Vg = g_V16 + hb;
    const int* mrow = mask + b * S_;
    const int* mflag = g_mflag + b * (S_ / 64);

    const uint32_t smb = (uint32_t)__cvta_generic_to_shared(sm);
    const int lrow8 = (lid & 7) + (lid & 8);
    const int lcol8 = (lid >> 4) << 3;

    // ---- prologue: Q tile (group 0), first K/V tile (group 1) ----
    {
        int row = t >> 1, half = (t & 1) * 32;
        size_t g = ((size_t)(q0 + row) << 6) + half;
        uint32_t so = (uint32_t)(row * RSTR + half) * 2;
        #pragma unroll
        for (int i = 0; i < 4; i++)
            cp_async16(sm + SM_Q + so + i * 16, Qg + g + i * 8);
    }
    CP_ASYNC_COMMIT();

    auto load_kv = [&](int st, int kt) {
        int r = t >> 2, seg = t & 3;
        size_t g = ((size_t)(kt * 64 + r) << 6) + seg * 16;
        char* stb = sm + SM_KV + st * KV_STAGE;
        uint32_t so = (uint32_t)(r * RSTR + seg * 16) * 2;
        cp_async16(stb + OFF_K + so,      Kg + g);
        cp_async16(stb + OFF_K + so + 16, Kg + g + 8);
        cp_async16(stb + OFF_V + so,      Vg + g);
        cp_async16(stb + OFF_V + so + 16, Vg + g + 8);
        if (t < 16)
            cp_async16(sm + SM_MK + st * 256 + t * 16, mrow + kt * 64 + t * 4);
    };

    load_kv(0, 0);
    CP_ASYNC_COMMIT();

    float o[8][4];
    #pragma unroll
    for (int i = 0; i < 8; i++)
        #pragma unroll
        for (int j = 0; j < 4; j++) o[i][j] = 0.f;
    float m0 = -1.0e30f, m1 = -1.0e30f, l0 = 0.f, l1 = 0.f;

    const int gr0 = q0 + w * 16 + lr;
    const int ntiles = 2 * qb + 2;

    for (int kt = 0; kt < ntiles; kt++) {
        const int st = kt & 1;
        if (kt + 1 < ntiles) load_kv(st ^ 1, kt + 1);
        CP_ASYNC_COMMIT();
        CP_ASYNC_WAIT1();
        __syncthreads();

        const bool active = (kt * 64 <= q0 + w * 16 + 15);
        if (active) {
            const uint32_t k32 = smb + SM_KV + st * KV_STAGE + OFF_K;
            const uint32_t v32 = smb + SM_KV + st * KV_STAGE + OFF_V;
            const int* mk = (const int*)(sm + SM_MK + st * 256);

            int rem = q0 + w * 16 + 15 - kt * 64;
            if (rem > 63) rem = 63;
            const int nlim = (rem >> 4) + 1;          // 1..4

            // ---- S = Q K^T (single-pass fp16; Q pre-scaled) ----
            float s[8][4];
            #pragma unroll
            for (int i = 0; i < 8; i++)
                #pragma unroll
                for (int j = 0; j < 4; j++) s[i][j] = 0.f;

            #pragma unroll
            for (int ks = 0; ks < 4; ks++) {
                const int ko = ks * 16;
                const uint32_t afo =
                    (uint32_t)((w * 16 + lrow8) * RSTR + ko + lcol8) * 2;
                uint32_t a0, a1, a2, a3;
                ldmatrix_x4(a0, a1, a2, a3, smb + SM_Q + afo);
                #pragma unroll
                for (int nfp = 0; nfp < 4; nfp++) {
                    if (nfp < nlim) {
                        const uint32_t bfo =
                            (uint32_t)((nfp * 16 + lrow8) * RSTR + ko + lcol8) * 2;
                        uint32_t b0, b1, b2, b3;
                        ldmatrix_x4(b0, b1, b2, b3, k32 + bfo);
                        mma_f16(s[2*nfp],   a0, a1, a2, a3, b0, b2);
                        mma_f16(s[2*nfp+1], a0, a1, a2, a3, b1, b3);
                    }
                }
            }

            // ---- masking (warp-uniform branches; no scaling needed) ----
            const bool diag = (kt >= 2 * qb);
            const int  fl   = mflag[kt];              // all 64 cols valid?
            if (diag | !fl) {
                if (fl) {
                    // causal-only (no smem mask reads)
                    #pragma unroll
                    for (int nf = 0; nf < 8; nf++) {
                        int c0 = kt * 64 + nf * 8 + 2 * lc, c1 = c0 + 1;
                        if (c0 > gr0)     s[nf][0] = -1.0e30f;
                        if (c1 > gr0)     s[nf][1] = -1.0e30f;
                        if (c0 > gr0 + 8) s[nf][2] = -1.0e30f;
                        if (c1 > gr0 + 8) s[nf][3] = -1.0e30f;
                    }
                } else {
                    #pragma unroll
                    for (int nf = 0; nf < 8; nf++) {
                        int ci = nf * 8 + 2 * lc;
                        int c0 = kt * 64 + ci, c1 = c0 + 1;
                        int mv0 = mk[ci], mv1 = mk[ci + 1];
                        if ((diag && c0 > gr0) || mv0 == 0)     s[nf][0] = -1.0e30f;
                        if ((diag && c1 > gr0) || mv1 == 0)     s[nf][1] = -1.0e30f;
                        if ((diag && c0 > gr0 + 8) || mv0 == 0) s[nf][2] = -1.0e30f;
                        if ((diag && c1 > gr0 + 8) || mv1 == 0) s[nf][3] = -1.0e30f;
                    }
                }
            }
            // fast path (non-diag, all valid): s used as-is

            // ---- online softmax (warp-local, exp2 domain) ----
            float mx0 = -1.0e30f, mx1 = -1.0e30f;
            #pragma unroll
            for (int nf = 0; nf < 8; nf++) {
                mx0 = fmaxf(mx0, fmaxf(s[nf][0], s[nf][1]));
                mx1 = fmaxf(mx1, fmaxf(s[nf][2], s[nf][3]));
            }
            mx0 = fmaxf(mx0, __shfl_xor_sync(0xffffffffu, mx0, 1));
            mx0 = fmaxf(mx0, __shfl_xor_sync(0xffffffffu, mx0, 2));
            mx1 = fmaxf(mx1, __shfl_xor_sync(0xffffffffu, mx1, 1));
            mx1 = fmaxf(mx1, __shfl_xor_sync(0xffffffffu, mx1, 2));
            float mn0 = fmaxf(m0, mx0), mn1 = fmaxf(m1, mx1);
            float alpha0 = exp2f(m0 - mn0), alpha1 = exp2f(m1 - mn1);
            m0 = mn0; m1 = mn1;

            float sum0 = 0.f, sum1 = 0.f;
            #pragma unroll
            for (int nf = 0; nf < 8; nf++) {
                float p;
                p = exp2f(s[nf][0] - mn0); s[nf][0] = p; sum0 += p;
                p = exp2f(s[nf][1] - mn0); s[nf][1] = p; sum0 += p;
                p = exp2f(s[nf][2] - mn1); s[nf][2] = p; sum1 += p;
                p = exp2f(s[nf][3] - mn1); s[nf][3] = p; sum1 += p;
            }
            sum0 += __shfl_xor_sync(0xffffffffu, sum0, 1);
            sum0 += __shfl_xor_sync(0xffffffffu, sum0, 2);
            sum1 += __shfl_xor_sync(0xffffffffu, sum1, 1);
            sum1 += __shfl_xor_sync(0xffffffffu, sum1, 2);
            l0 = l0 * alpha0 + sum0;
            l1 = l1 * alpha1 + sum1;

            #pragma unroll
            for (int nf = 0; nf < 8; nf++) {
                o[nf][0] *= alpha0; o[nf][1] *= alpha0;
                o[nf][2] *= alpha1; o[nf][3] *= alpha1;
            }

            // ---- O += P V (single-pass fp16) ----
            const int g  = lid >> 3;
            const int lrow = lid & 7;
            #pragma unroll
            for (int ks = 0; ks < 4; ks++) {
                if (ks < nlim) {
                    uint32_t p0 = packhf(s[2*ks][0],   s[2*ks][1]);
                    uint32_t p1 = packhf(s[2*ks][2],   s[2*ks][3]);
                    uint32_t p2 = packhf(s[2*ks+1][0], s[2*ks+1][1]);
                    uint32_t p3 = packhf(s[2*ks+1][2], s[2*ks+1][3]);
                    #pragma unroll
                    for (int nfp = 0; nfp < 4; nfp++) {
                        uint32_t offB = (uint32_t)((ks * 16 + (g & 1) * 8 + lrow) * RSTR
                                                   + nfp * 16 + (g >> 1) * 8) * 2;
                        uint32_t b0, b1, b2, b3;
                        ldmatrix_x4_trans(b0, b1, b2, b3, v32 + offB);
                        mma_f16(o[2*nfp],   p0, p1, p2, p3, b0, b1);
                        mma_f16(o[2*nfp+1], p0, p1, p2, p3, b2, b3);
                    }
                }
            }
        }
        __syncthreads();
    }

    // ---- epilogue: normalize + store (fp32) ----
    float inv0 = 1.0f / l0, inv1 = 1.0f / l1;
    #pragma unroll
    for (int nf = 0; nf < 8; nf++) {
        int col = h * DK_ + nf * 8 + 2 * lc;
        float2 r0, r1;
        r0.x = o[nf][0] * inv0; r0.y = o[nf][1] * inv0;
        r1.x = o[nf][2] * inv1; r1.y = o[nf][3] * inv1;
        *(float2*)&out[(size_t)(b * S_ + gr0) * D_ + col] = r0;
        *(float2*)&out[(size_t)(b * S_ + gr0 + 8) * D_ + col] = r1;
    }
}

// ---------------------------------------------------------------------------
// Launch
// inputs: query, key, value, att_mask, Wq, bq, Wk, bk, Wv, bv
// ---------------------------------------------------------------------------
extern "C" void kernel_launch(void* const* d_in, const int* in_sizes, int n_in,
                              void* d_out, int out_size) {
    (void)in_sizes; (void)n_in; (void)out_size;
    const float* query = (const float*)d_in[0];
    const float* key   = (const float*)d_in[1];
    const float* value = (const float*)d_in[2];
    const int*   amask = (const int*)  d_in[3];
    const float* Wq = (const float*)d_in[4];
    const float* bq = (const float*)d_in[5];
    const float* Wk = (const float*)d_in[6];
    const float* bk = (const float*)d_in[7];
    const float* Wv = (const float*)d_in[8];
    const float* bv = (const float*)d_in[9];
    float* out = (float*)d_out;

    static uint16_t *x16 = nullptr, *w16 = nullptr;
    if (!x16) {
        cudaGetSymbolAddress((void**)&x16, g_X16);
        cudaGetSymbolAddress((void**)&w16, g_W16);
        cudaFuncSetAttribute(attn_mma,
                             cudaFuncAttributeMaxDynamicSharedMemorySize, ATTN_SMEM);
    }

    const int NX4 = M_TOT * D_ / 4;   // 1048576
    const int NW4 = D_ * D_ / 4;      // 262144
    dim3 gx((NX4 + 255) / 256, 1, 3);
    cvt_f16_kernel<<<gx, 256>>>(query, key, value, x16, NX4);
    dim3 gw((NW4 + 255) / 256, 1, 3);
    cvt_f16_kernel<<<gw, 256>>>(Wq, Wk, Wv, w16, NW4);
    mask_flags_kernel<<<1, 64>>>(amask);

    dim3 gproj(D_ / PBN, M_TOT / PBM, 3);   // (8, 32, 3)
    qkv_proj_mma<<<gproj, 256>>>(bq, bk, bv);

    dim3 gattn(S_ / 128, H_, B_);            // (8, 16, 4)
    attn_mma<<<gattn, 256, ATTN_SMEM>>>(amask, out);
}